// round 1
// baseline (speedup 1.0000x reference)
#include <cuda_runtime.h>
#include <math.h>

// Problem shape (fixed by the dataset)
#define D       256
#define NROWS   16384
#define KCODES  4096

// Main GEMM-argmin tiling
#define BM      128      // ze rows per CTA
#define BN      128      // codes per k-tile
#define DC      32       // D-chunk staged through smem
#define TM      8        // rows per thread
#define TN      8        // codes per thread
#define SZE     260      // padded ze smem row stride (floats)
#define SCB     36       // padded cb smem row stride (floats)
#define KSPLIT  4        // K split across blockIdx.y

// Scratch (no device mallocs allowed -> __device__ globals)
__device__ float g_cbnorm[KCODES];
__device__ int   g_counts[KCODES];
__device__ float g_loss;
__device__ float g_pmin[KSPLIT][NROWS];
__device__ int   g_pidx[KSPLIT][NROWS];

// ---------------------------------------------------------------------------
// Kernel 1: codebook squared norms + zero counts/loss. Warp per codeword.
// ---------------------------------------------------------------------------
__global__ void prep_kernel(const float* __restrict__ cb) {
    const int tid = threadIdx.x;
    const int gid = blockIdx.x * blockDim.x + tid;
    if (gid < KCODES) g_counts[gid] = 0;
    if (gid == 0) g_loss = 0.f;

    const int warp = tid >> 5, lane = tid & 31;
    const int code = blockIdx.x * 8 + warp;
    if (code < KCODES) {
        const float* row = cb + (size_t)code * D;
        float s = 0.f;
#pragma unroll
        for (int i = 0; i < D / 32; i++) {
            float v = row[lane + i * 32];
            s = fmaf(v, v, s);
        }
#pragma unroll
        for (int o = 16; o; o >>= 1) s += __shfl_xor_sync(0xffffffffu, s, o);
        if (lane == 0) g_cbnorm[code] = s;
    }
}

// ---------------------------------------------------------------------------
// Kernel 2: fp32 tiled distance-GEMM with fused running argmin.
// score(k) = ||cb_k||^2 - 2 * <ze_row, cb_k>   (row-constant ||ze||^2 dropped)
// grid = (NROWS/BM, KSPLIT), 256 threads (16x16), 8x8 micro-tile.
// ---------------------------------------------------------------------------
extern __shared__ float smem[];

__global__ void __launch_bounds__(256)
argmin_kernel(const float* __restrict__ ze, const float* __restrict__ cb) {
    float* s_ze = smem;                 // BM x SZE
    float* s_cb = smem + BM * SZE;      // BN x SCB

    const int tid  = threadIdx.x;
    const int tx   = tid & 15;          // code group
    const int ty   = tid >> 4;          // row group
    const int row0 = blockIdx.x * BM;
    const int kbase = blockIdx.y * (KCODES / KSPLIT);

    // Load the full BM x D ze tile once (float4, coalesced, padded stride)
    {
        const float4* zg = (const float4*)(ze + (size_t)row0 * D);
#pragma unroll
        for (int it = 0; it < (BM * D / 4) / 256; it++) {   // 32 iters
            int idx = tid + it * 256;
            int r   = idx >> 6;          // D/4 = 64 float4 per row
            int c4  = idx & 63;
            float4 v = zg[r * (D / 4) + c4];
            *(float4*)&s_ze[r * SZE + c4 * 4] = v;
        }
    }

    float best[TM];
    int   bidx[TM];
#pragma unroll
    for (int r = 0; r < TM; r++) { best[r] = 3.4e38f; bidx[r] = 0; }

    for (int kt = 0; kt < KCODES / KSPLIT; kt += BN) {
        float acc[TM][TN];
#pragma unroll
        for (int r = 0; r < TM; r++)
#pragma unroll
            for (int c = 0; c < TN; c++) acc[r][c] = 0.f;

        for (int dc = 0; dc < D; dc += DC) {
            __syncthreads();
            // Stage BN x DC codebook chunk into smem
            {
                const float4* cg = (const float4*)cb;
#pragma unroll
                for (int it = 0; it < (BN * DC / 4) / 256; it++) {  // 4 iters
                    int idx  = tid + it * 256;
                    int code = idx >> 3;     // DC/4 = 8 float4 per code
                    int c4   = idx & 7;
                    float4 v = cg[(size_t)(kbase + kt + code) * (D / 4) + (dc >> 2) + c4];
                    *(float4*)&s_cb[code * SCB + c4 * 4] = v;
                }
            }
            __syncthreads();

#pragma unroll 2
            for (int d4 = 0; d4 < DC / 4; d4++) {
                float4 a[TM];
#pragma unroll
                for (int r = 0; r < TM; r++)
                    a[r] = *(const float4*)&s_ze[(ty * TM + r) * SZE + dc + d4 * 4];
                float4 b[TN];
#pragma unroll
                for (int c = 0; c < TN; c++)
                    b[c] = *(const float4*)&s_cb[(c * 16 + tx) * SCB + d4 * 4];
#pragma unroll
                for (int r = 0; r < TM; r++)
#pragma unroll
                    for (int c = 0; c < TN; c++) {
                        acc[r][c] = fmaf(a[r].x, b[c].x, acc[r][c]);
                        acc[r][c] = fmaf(a[r].y, b[c].y, acc[r][c]);
                        acc[r][c] = fmaf(a[r].z, b[c].z, acc[r][c]);
                        acc[r][c] = fmaf(a[r].w, b[c].w, acc[r][c]);
                    }
            }
        }

        // Fold this k-tile into the running per-row min
#pragma unroll
        for (int c = 0; c < TN; c++) {
            int k = kbase + kt + c * 16 + tx;
            float cn = g_cbnorm[k];
#pragma unroll
            for (int r = 0; r < TM; r++) {
                float s = fmaf(-2.f, acc[r][c], cn);
                if (s < best[r]) { best[r] = s; bidx[r] = k; }
            }
        }
    }

    // Reduce across the 16 tx-lanes sharing each row (shuffle, tie -> lower k)
#pragma unroll
    for (int r = 0; r < TM; r++) {
        float v = best[r];
        int   i = bidx[r];
#pragma unroll
        for (int o = 8; o; o >>= 1) {
            float v2 = __shfl_xor_sync(0xffffffffu, v, o);
            int   i2 = __shfl_xor_sync(0xffffffffu, i, o);
            if (v2 < v || (v2 == v && i2 < i)) { v = v2; i = i2; }
        }
        if (tx == 0) {
            g_pmin[blockIdx.y][row0 + ty * TM + r] = v;
            g_pidx[blockIdx.y][row0 + ty * TM + r] = i;
        }
    }
}

// ---------------------------------------------------------------------------
// Kernel 3: combine K-split partials; gather zq, write indices, MSE sum, counts.
// Warp per row.
// ---------------------------------------------------------------------------
__global__ void gather_kernel(const float* __restrict__ ze,
                              const float* __restrict__ cb,
                              float* __restrict__ out) {
    const int warp = threadIdx.x >> 5, lane = threadIdx.x & 31;
    const int row = blockIdx.x * 8 + warp;
    if (row >= NROWS) return;

    float bv = g_pmin[0][row];
    int   bi = g_pidx[0][row];
#pragma unroll
    for (int p = 1; p < KSPLIT; p++) {
        float v = g_pmin[p][row];
        int   i = g_pidx[p][row];
        if (v < bv || (v == bv && i < bi)) { bv = v; bi = i; }
    }

    if (lane == 0) {
        out[row] = (float)bi;               // indices, cast to output dtype
        atomicAdd(&g_counts[bi], 1);
    }

    const float* zr = ze + (size_t)row * D;
    const float* cr = cb + (size_t)bi * D;
    float* qr = out + NROWS + (size_t)row * D;
    float s = 0.f;
#pragma unroll
    for (int i = 0; i < D / 32; i++) {
        float c = cr[lane + i * 32];
        float z = zr[lane + i * 32];
        qr[lane + i * 32] = c;
        float dd = c - z;
        s = fmaf(dd, dd, s);
    }
#pragma unroll
    for (int o = 16; o; o >>= 1) s += __shfl_xor_sync(0xffffffffu, s, o);
    if (lane == 0) atomicAdd(&g_loss, s);
}

// ---------------------------------------------------------------------------
// Kernel 4: scalars — vq_e_loss, vq_commit_loss (same value), perplexity.
// Faithful to the reference's probs = counts/10 (overflows to +inf, same as
// the fp32 reference).
// ---------------------------------------------------------------------------
__global__ void finalize_kernel(float* __restrict__ out) {
    __shared__ float red[256];
    float h = 0.f;
    for (int k = threadIdx.x; k < KCODES; k += 256) {
        float p = (float)g_counts[k] / 10.0f;
        h += p * logf(p + 1e-10f);
    }
    red[threadIdx.x] = h;
    __syncthreads();
    for (int o = 128; o; o >>= 1) {
        if (threadIdx.x < o) red[threadIdx.x] += red[threadIdx.x + o];
        __syncthreads();
    }
    if (threadIdx.x == 0) {
        float loss = g_loss / (float)((size_t)NROWS * D);
        const size_t base = (size_t)NROWS + (size_t)NROWS * D;
        out[base + 0] = loss;       // vq_e_loss
        out[base + 1] = loss;       // vq_commit_loss (numerically identical)
        out[base + 2] = expf(-red[0]);
    }
}

// ---------------------------------------------------------------------------
extern "C" void kernel_launch(void* const* d_in, const int* in_sizes, int n_in,
                              void* d_out, int out_size) {
    const float* ze = (const float*)d_in[0];
    const float* cb = (const float*)d_in[1];
    float* out = (float*)d_out;

    const size_t smem_bytes = (size_t)(BM * SZE + BN * SCB) * sizeof(float);
    cudaFuncSetAttribute(argmin_kernel,
                         cudaFuncAttributeMaxDynamicSharedMemorySize,
                         (int)smem_bytes);

    prep_kernel<<<KCODES / 8, 256>>>(cb);

    dim3 grid(NROWS / BM, KSPLIT);
    argmin_kernel<<<grid, 256, smem_bytes>>>(ze, cb);

    gather_kernel<<<NROWS / 8, 256>>>(ze, cb, out);
    finalize_kernel<<<1, 256>>>(out);
}

// round 3
// speedup vs baseline: 3.1544x; 3.1544x over previous
#include <cuda_runtime.h>
#include <cuda_bf16.h>
#include <math.h>
#include <stdint.h>

// Problem shape (fixed)
#define D       256
#define NROWS   16384
#define KCODES  4096

// Pass-1 GEMM tiling
#define BM      128
#define BN      256
#define KC      64                 // bf16 elems per staged chunk (=128B rows)
#define NCHUNK  (D / KC)           // 4
#define KSPLIT  (KCODES / BN)      // 16
#define MARGIN  0.75f

// smem: stage = A(128x128B=16K) + B(256x128B=32K) = 48K, double buffered
#define STAGE_BYTES   49152
#define A_OFF         0
#define B_OFF         16384
#define SMEM_CBN      (2 * STAGE_BYTES)
#define SMEM_TOTAL    (SMEM_CBN + 1024)

#define SWZ(x) ((x) ^ (((x) >> 3) & 0x70))

// ---------------------------------------------------------------------------
__device__ __forceinline__ uint32_t smem_u32(const void* p) {
    uint32_t a;
    asm("{ .reg .u64 t; cvta.to.shared.u64 t, %1; cvt.u32.u64 %0, t; }" : "=r"(a) : "l"(p));
    return a;
}
#define CP_ASYNC16(dst, src) \
    asm volatile("cp.async.cg.shared.global [%0], [%1], 16;" :: "r"(dst), "l"(src))
#define CP_COMMIT() asm volatile("cp.async.commit_group;" ::: "memory")
#define CP_WAIT(n)  asm volatile("cp.async.wait_group %0;" :: "n"(n) : "memory")
#define LDSM4(r0, r1, r2, r3, addr) \
    asm volatile("ldmatrix.sync.aligned.m8n8.x4.shared.b16 {%0,%1,%2,%3}, [%4];" \
                 : "=r"(r0), "=r"(r1), "=r"(r2), "=r"(r3) : "r"(addr))
#define MMA_BF16(c, a, b0, b1) \
    asm volatile("mma.sync.aligned.m16n8k16.row.col.f32.bf16.bf16.f32 " \
                 "{%0,%1,%2,%3}, {%4,%5,%6,%7}, {%8,%9}, {%0,%1,%2,%3};" \
                 : "+f"((c)[0]), "+f"((c)[1]), "+f"((c)[2]), "+f"((c)[3]) \
                 : "r"((a)[0]), "r"((a)[1]), "r"((a)[2]), "r"((a)[3]), "r"(b0), "r"(b1))

// ---------------------------------------------------------------------------
// Scratch
// ---------------------------------------------------------------------------
__device__ __nv_bfloat16 g_zeB[NROWS * D];
__device__ __nv_bfloat16 g_cbB[KCODES * D];
__device__ float g_cbnorm[KCODES];
__device__ int   g_counts[KCODES];
__device__ float g_loss;
__device__ float g_tval[KSPLIT * NROWS * 3];
__device__ int   g_tidx[KSPLIT * NROWS * 3];

// ---------------------------------------------------------------------------
// Convert ze -> bf16
// ---------------------------------------------------------------------------
__global__ void conv_ze_kernel(const float* __restrict__ ze) {
    int idx = blockIdx.x * 256 + threadIdx.x;     // float4 index
    float4 v = ((const float4*)ze)[idx];
    __nv_bfloat162* o = (__nv_bfloat162*)g_zeB;
    o[idx * 2 + 0] = __floats2bfloat162_rn(v.x, v.y);
    o[idx * 2 + 1] = __floats2bfloat162_rn(v.z, v.w);
}

// ---------------------------------------------------------------------------
// Codebook: bf16 convert + fp32 norms + zero counts/loss. Warp per code.
// ---------------------------------------------------------------------------
__global__ void prep_cb_kernel(const float* __restrict__ cb) {
    const int tid = threadIdx.x;
    const int gid = blockIdx.x * 256 + tid;
    if (gid < KCODES) g_counts[gid] = 0;
    if (gid == 0) g_loss = 0.f;

    const int warp = tid >> 5, lane = tid & 31;
    const int code = blockIdx.x * 8 + warp;
    const float* row = cb + (size_t)code * D;
    float s = 0.f;
#pragma unroll
    for (int i = 0; i < D / 32; i++) {
        int j = lane + i * 32;
        float x = row[j];
        g_cbB[(size_t)code * D + j] = __float2bfloat16_rn(x);
        s = fmaf(x, x, s);
    }
#pragma unroll
    for (int o = 16; o; o >>= 1) s += __shfl_xor_sync(0xffffffffu, s, o);
    if (lane == 0) g_cbnorm[code] = s;
}

// ---------------------------------------------------------------------------
// top-3 insert (ascending)
// ---------------------------------------------------------------------------
__device__ __forceinline__ void ins3(float* tv, int* ti, float v, int id) {
    if (v < tv[0]) {
        tv[2] = tv[1]; ti[2] = ti[1];
        tv[1] = tv[0]; ti[1] = ti[0];
        tv[0] = v;     ti[0] = id;
    } else if (v < tv[1]) {
        tv[2] = tv[1]; ti[2] = ti[1];
        tv[1] = v;     ti[1] = id;
    } else if (v < tv[2]) {
        tv[2] = v;     ti[2] = id;
    }
}

// ---------------------------------------------------------------------------
// Pass 1: bf16 mma.sync distance GEMM, fused top-3 argmin per 256-code split.
// grid = (NROWS/BM, KSPLIT), 256 threads (8 warps, 2m x 4n).
// ---------------------------------------------------------------------------
extern __shared__ char dyn_smem[];

__device__ __forceinline__ void copy_chunk(uint32_t st, int ch, int row0,
                                           int kbase, int tid) {
    const __nv_bfloat16* Az = g_zeB + (size_t)row0 * D + ch * KC;
    const __nv_bfloat16* Bz = g_cbB + (size_t)kbase * D + ch * KC;
#pragma unroll
    for (int it = 0; it < 4; it++) {           // A: 128 rows x 8 granules
        int idx = tid + it * 256;
        int r = idx >> 3, g = idx & 7;
        CP_ASYNC16(st + A_OFF + SWZ((uint32_t)(r * 128 + g * 16)),
                   Az + (size_t)r * D + g * 8);
    }
#pragma unroll
    for (int it = 0; it < 8; it++) {           // B: 256 rows x 8 granules
        int idx = tid + it * 256;
        int r = idx >> 3, g = idx & 7;
        CP_ASYNC16(st + B_OFF + SWZ((uint32_t)(r * 128 + g * 16)),
                   Bz + (size_t)r * D + g * 8);
    }
}

__global__ void __launch_bounds__(256, 1) pass1_kernel() {
    const int tid  = threadIdx.x;
    const int warp = tid >> 5, lane = tid & 31;
    const int wm = warp & 1, wn = warp >> 1;   // 2 x 4 warp grid
    const int row0 = blockIdx.x * BM;
    const int kbase = blockIdx.y * BN;
    const uint32_t sb = smem_u32(dyn_smem);
    float* s_cbn = (float*)(dyn_smem + SMEM_CBN);

    if (tid < BN) s_cbn[tid] = g_cbnorm[kbase + tid];

    copy_chunk(sb, 0, row0, kbase, tid);
    CP_COMMIT();

    float c[4][8][4];
#pragma unroll
    for (int i = 0; i < 4; i++)
#pragma unroll
        for (int j = 0; j < 8; j++)
#pragma unroll
            for (int q = 0; q < 4; q++) c[i][j][q] = 0.f;

    for (int ch = 0; ch < NCHUNK; ch++) {
        if (ch + 1 < NCHUNK) {
            copy_chunk(sb + ((ch + 1) & 1) * STAGE_BYTES, ch + 1, row0, kbase, tid);
            CP_COMMIT();
            CP_WAIT(1);
        } else {
            CP_WAIT(0);
        }
        __syncthreads();

        const uint32_t st = sb + (ch & 1) * STAGE_BYTES;
#pragma unroll
        for (int ks = 0; ks < KC / 16; ks++) {
            uint32_t a[4][4];
#pragma unroll
            for (int i = 0; i < 4; i++) {
                uint32_t addr = st + A_OFF +
                    SWZ((uint32_t)((wm * 64 + i * 16 + (lane & 15)) * 128 +
                                   ks * 32 + (lane >> 4) * 16));
                LDSM4(a[i][0], a[i][1], a[i][2], a[i][3], addr);
            }
#pragma unroll
            for (int j = 0; j < 4; j++) {
                uint32_t b0, b1, b2, b3;
                uint32_t addr = st + B_OFF +
                    SWZ((uint32_t)((wn * 64 + j * 16 + (lane & 15)) * 128 +
                                   ks * 32 + (lane >> 4) * 16));
                LDSM4(b0, b1, b2, b3, addr);
#pragma unroll
                for (int i = 0; i < 4; i++) {
                    MMA_BF16(c[i][2 * j + 0], a[i], b0, b2);
                    MMA_BF16(c[i][2 * j + 1], a[i], b1, b3);
                }
            }
        }
        __syncthreads();
    }

    // ---- Epilogue: score = cbnorm - 2*dot; per-row top-3 ----
    float tv[8][3];
    int   ti[8][3];
#pragma unroll
    for (int r = 0; r < 8; r++)
#pragma unroll
        for (int k = 0; k < 3; k++) { tv[r][k] = 3.4e38f; ti[r][k] = 0; }

#pragma unroll
    for (int i = 0; i < 4; i++)
#pragma unroll
        for (int jj = 0; jj < 8; jj++)
#pragma unroll
            for (int q = 0; q < 4; q++) {
                int col = wn * 64 + jj * 8 + (lane & 3) * 2 + (q & 1);
                float s = fmaf(-2.f, c[i][jj][q], s_cbn[col]);
                int ri = i * 2 + (q >> 1);
                ins3(tv[ri], ti[ri], s, kbase + col);
            }

    // merge across the 4 lanes sharing each row (lanes differ in l&3)
#pragma unroll
    for (int off = 1; off <= 2; off <<= 1) {
#pragma unroll
        for (int r = 0; r < 8; r++) {
            float pv[3]; int pi[3];
#pragma unroll
            for (int k = 0; k < 3; k++) {
                pv[k] = __shfl_xor_sync(0xffffffffu, tv[r][k], off);
                pi[k] = __shfl_xor_sync(0xffffffffu, ti[r][k], off);
            }
#pragma unroll
            for (int k = 0; k < 3; k++) ins3(tv[r], ti[r], pv[k], pi[k]);
        }
    }

    // stage per-(row, wn) lists into smem (reuse stage0 region)
    float* smv = (float*)dyn_smem;               // [128][4][3]
    int*   smi = (int*)(dyn_smem + 128 * 4 * 3 * 4);
    if ((lane & 3) == 0) {
        int g = lane >> 2;
#pragma unroll
        for (int i = 0; i < 4; i++)
#pragma unroll
            for (int sub = 0; sub < 2; sub++) {
                int ri = i * 2 + sub;
                int r = wm * 64 + i * 16 + g + sub * 8;
#pragma unroll
                for (int k = 0; k < 3; k++) {
                    smv[(r * 4 + wn) * 3 + k] = tv[ri][k];
                    smi[(r * 4 + wn) * 3 + k] = ti[ri][k];
                }
            }
    }
    __syncthreads();

    if (tid < BM) {
        float fv[3] = {3.4e38f, 3.4e38f, 3.4e38f};
        int   fi[3] = {0, 0, 0};
#pragma unroll
        for (int w = 0; w < 4; w++)
#pragma unroll
            for (int k = 0; k < 3; k++)
                ins3(fv, fi, smv[(tid * 4 + w) * 3 + k], smi[(tid * 4 + w) * 3 + k]);
        size_t base = ((size_t)blockIdx.y * NROWS + row0 + tid) * 3;
#pragma unroll
        for (int k = 0; k < 3; k++) {
            g_tval[base + k] = fv[k];
            g_tidx[base + k] = fi[k];
        }
    }
}

// ---------------------------------------------------------------------------
// Refine: exact fp32 re-scoring of candidates; gather zq, indices, loss, counts.
// Warp per row.
// ---------------------------------------------------------------------------
__global__ void refine_kernel(const float* __restrict__ ze,
                              const float* __restrict__ cb,
                              float* __restrict__ out) {
    const int warp = threadIdx.x >> 5, lane = threadIdx.x & 31;
    const int row = blockIdx.x * 8 + warp;

    // global min of approximate candidate scores
    float vmin = 3.4e38f;
#pragma unroll 4
    for (int s = 0; s < KSPLIT; s++) {
        size_t base = ((size_t)s * NROWS + row) * 3;
#pragma unroll
        for (int k = 0; k < 3; k++) vmin = fminf(vmin, g_tval[base + k]);
    }

    const float4* zef = (const float4*)ze;
    const float4* cbf = (const float4*)cb;
    float bestv = 3.4e38f;
    int   besti = 0x7fffffff;

    for (int s = 0; s < KSPLIT; s++) {
        size_t base = ((size_t)s * NROWS + row) * 3;
#pragma unroll
        for (int k = 0; k < 3; k++) {
            float av = g_tval[base + k];
            if (av <= vmin + MARGIN) {
                int idx = g_tidx[base + k];
                float dot = 0.f;
#pragma unroll
                for (int u = 0; u < 2; u++) {
                    float4 z = zef[(size_t)row * 64 + lane * 2 + u];
                    float4 e = cbf[(size_t)idx * 64 + lane * 2 + u];
                    dot = fmaf(z.x, e.x, dot);
                    dot = fmaf(z.y, e.y, dot);
                    dot = fmaf(z.z, e.z, dot);
                    dot = fmaf(z.w, e.w, dot);
                }
#pragma unroll
                for (int o = 16; o; o >>= 1)
                    dot += __shfl_xor_sync(0xffffffffu, dot, o);
                float sc = fmaf(-2.f, dot, g_cbnorm[idx]);
                if (sc < bestv || (sc == bestv && idx < besti)) {
                    bestv = sc; besti = idx;
                }
            }
        }
    }

    if (lane == 0) {
        out[row] = (float)besti;
        atomicAdd(&g_counts[besti], 1);
    }

    const float* zr = ze + (size_t)row * D;
    const float* cr = cb + (size_t)besti * D;
    float* qr = out + NROWS + (size_t)row * D;
    float sl = 0.f;
#pragma unroll
    for (int i = 0; i < D / 32; i++) {
        float cv = cr[lane + i * 32];
        float zv = zr[lane + i * 32];
        qr[lane + i * 32] = cv;
        float dd = cv - zv;
        sl = fmaf(dd, dd, sl);
    }
#pragma unroll
    for (int o = 16; o; o >>= 1) sl += __shfl_xor_sync(0xffffffffu, sl, o);
    if (lane == 0) atomicAdd(&g_loss, sl);
}

// ---------------------------------------------------------------------------
// Scalars (losses identical; perplexity faithful to the /10 reference quirk)
// ---------------------------------------------------------------------------
__global__ void finalize_kernel(float* __restrict__ out) {
    __shared__ float red[256];
    float h = 0.f;
    for (int k = threadIdx.x; k < KCODES; k += 256) {
        float p = (float)g_counts[k] / 10.0f;
        h += p * logf(p + 1e-10f);
    }
    red[threadIdx.x] = h;
    __syncthreads();
    for (int o = 128; o; o >>= 1) {
        if (threadIdx.x < o) red[threadIdx.x] += red[threadIdx.x + o];
        __syncthreads();
    }
    if (threadIdx.x == 0) {
        float loss = g_loss / (float)((size_t)NROWS * D);
        const size_t base = (size_t)NROWS + (size_t)NROWS * D;
        out[base + 0] = loss;
        out[base + 1] = loss;
        out[base + 2] = expf(-red[0]);
    }
}

// ---------------------------------------------------------------------------
extern "C" void kernel_launch(void* const* d_in, const int* in_sizes, int n_in,
                              void* d_out, int out_size) {
    const float* ze = (const float*)d_in[0];
    const float* cb = (const float*)d_in[1];
    float* out = (float*)d_out;

    cudaFuncSetAttribute(pass1_kernel,
                         cudaFuncAttributeMaxDynamicSharedMemorySize, SMEM_TOTAL);

    conv_ze_kernel<<<(NROWS * D / 4) / 256, 256>>>(ze);
    prep_cb_kernel<<<KCODES / 8, 256>>>(cb);

    dim3 grid(NROWS / BM, KSPLIT);
    pass1_kernel<<<grid, 256, SMEM_TOTAL>>>();

    refine_kernel<<<NROWS / 8, 256>>>(ze, cb, out);
    finalize_kernel<<<1, 256>>>(out);
}

// round 4
// speedup vs baseline: 4.1914x; 1.3288x over previous
#include <cuda_runtime.h>
#include <cuda_bf16.h>
#include <math.h>
#include <stdint.h>

// Problem shape (fixed)
#define D       256
#define NROWS   16384
#define KCODES  4096

// Pass-1 GEMM tiling: CTA 64x256, 8 warps (2m x 4n), warp tile 32x64
#define BM      64
#define BN      256
#define KC      64                 // bf16 elems per staged chunk (=128B rows)
#define NCHUNK  (D / KC)           // 4
#define KSPLIT  (KCODES / BN)      // 16
#define MARGIN  0.75f

// smem: stage = A(64x128B=8K) + B(256x128B=32K) = 40K, double buffered
#define STAGE_BYTES   40960
#define A_OFF         0
#define B_OFF         8192
#define SMEM_CBN      (2 * STAGE_BYTES)
#define SMEM_TOTAL    (SMEM_CBN + 1024)

#define SWZ(x) ((x) ^ (((x) >> 3) & 0x70))

// ---------------------------------------------------------------------------
__device__ __forceinline__ uint32_t smem_u32(const void* p) {
    uint32_t a;
    asm("{ .reg .u64 t; cvta.to.shared.u64 t, %1; cvt.u32.u64 %0, t; }" : "=r"(a) : "l"(p));
    return a;
}
#define CP_ASYNC16(dst, src) \
    asm volatile("cp.async.cg.shared.global [%0], [%1], 16;" :: "r"(dst), "l"(src))
#define CP_COMMIT() asm volatile("cp.async.commit_group;" ::: "memory")
#define CP_WAIT(n)  asm volatile("cp.async.wait_group %0;" :: "n"(n) : "memory")
#define LDSM4(r0, r1, r2, r3, addr) \
    asm volatile("ldmatrix.sync.aligned.m8n8.x4.shared.b16 {%0,%1,%2,%3}, [%4];" \
                 : "=r"(r0), "=r"(r1), "=r"(r2), "=r"(r3) : "r"(addr))
#define MMA_BF16(c, a, b0, b1) \
    asm volatile("mma.sync.aligned.m16n8k16.row.col.f32.bf16.bf16.f32 " \
                 "{%0,%1,%2,%3}, {%4,%5,%6,%7}, {%8,%9}, {%0,%1,%2,%3};" \
                 : "+f"((c)[0]), "+f"((c)[1]), "+f"((c)[2]), "+f"((c)[3]) \
                 : "r"((a)[0]), "r"((a)[1]), "r"((a)[2]), "r"((a)[3]), "r"(b0), "r"(b1))

// ---------------------------------------------------------------------------
// Scratch
// ---------------------------------------------------------------------------
__device__ __nv_bfloat16 g_zeB[NROWS * D];
__device__ __nv_bfloat16 g_cbB[KCODES * D];
__device__ float g_cbnorm[KCODES];
__device__ int   g_counts[KCODES];
__device__ float g_loss;
__device__ unsigned int g_done;
__device__ float g_tval[KSPLIT * NROWS * 3];
__device__ int   g_tidx[KSPLIT * NROWS * 3];

// ---------------------------------------------------------------------------
// Convert ze -> bf16
// ---------------------------------------------------------------------------
__global__ void conv_ze_kernel(const float* __restrict__ ze) {
    int idx = blockIdx.x * 256 + threadIdx.x;     // float4 index
    float4 v = ((const float4*)ze)[idx];
    __nv_bfloat162* o = (__nv_bfloat162*)g_zeB;
    o[idx * 2 + 0] = __floats2bfloat162_rn(v.x, v.y);
    o[idx * 2 + 1] = __floats2bfloat162_rn(v.z, v.w);
}

// ---------------------------------------------------------------------------
// Codebook: bf16 convert + fp32 norms + zero counts/loss/ticket. Warp per code.
// ---------------------------------------------------------------------------
__global__ void prep_cb_kernel(const float* __restrict__ cb) {
    const int tid = threadIdx.x;
    const int gid = blockIdx.x * 256 + tid;
    if (gid < KCODES) g_counts[gid] = 0;
    if (gid == 0) { g_loss = 0.f; g_done = 0u; }

    const int warp = tid >> 5, lane = tid & 31;
    const int code = blockIdx.x * 8 + warp;
    const float* row = cb + (size_t)code * D;
    float s = 0.f;
#pragma unroll
    for (int i = 0; i < D / 32; i++) {
        int j = lane + i * 32;
        float x = row[j];
        g_cbB[(size_t)code * D + j] = __float2bfloat16_rn(x);
        s = fmaf(x, x, s);
    }
#pragma unroll
    for (int o = 16; o; o >>= 1) s += __shfl_xor_sync(0xffffffffu, s, o);
    if (lane == 0) g_cbnorm[code] = s;
}

// ---------------------------------------------------------------------------
// top-3 insert (ascending)
// ---------------------------------------------------------------------------
__device__ __forceinline__ void ins3(float* tv, int* ti, float v, int id) {
    if (v < tv[0]) {
        tv[2] = tv[1]; ti[2] = ti[1];
        tv[1] = tv[0]; ti[1] = ti[0];
        tv[0] = v;     ti[0] = id;
    } else if (v < tv[1]) {
        tv[2] = tv[1]; ti[2] = ti[1];
        tv[1] = v;     ti[1] = id;
    } else if (v < tv[2]) {
        tv[2] = v;     ti[2] = id;
    }
}

// ---------------------------------------------------------------------------
// Pass 1: bf16 mma.sync distance GEMM, fused top-3 per 256-code split.
// grid = (NROWS/BM, KSPLIT), 256 threads, 2 CTAs/SM.
// ---------------------------------------------------------------------------
extern __shared__ char dyn_smem[];

__device__ __forceinline__ void copy_chunk(uint32_t st, int ch, int row0,
                                           int kbase, int tid) {
    const __nv_bfloat16* Az = g_zeB + (size_t)row0 * D + ch * KC;
    const __nv_bfloat16* Bz = g_cbB + (size_t)kbase * D + ch * KC;
#pragma unroll
    for (int it = 0; it < 2; it++) {           // A: 64 rows x 8 granules
        int idx = tid + it * 256;
        int r = idx >> 3, g = idx & 7;
        CP_ASYNC16(st + A_OFF + SWZ((uint32_t)(r * 128 + g * 16)),
                   Az + (size_t)r * D + g * 8);
    }
#pragma unroll
    for (int it = 0; it < 8; it++) {           // B: 256 rows x 8 granules
        int idx = tid + it * 256;
        int r = idx >> 3, g = idx & 7;
        CP_ASYNC16(st + B_OFF + SWZ((uint32_t)(r * 128 + g * 16)),
                   Bz + (size_t)r * D + g * 8);
    }
}

__global__ void __launch_bounds__(256, 2) pass1_kernel() {
    const int tid  = threadIdx.x;
    const int warp = tid >> 5, lane = tid & 31;
    const int wm = warp & 1, wn = warp >> 1;   // 2 x 4 warp grid
    const int row0 = blockIdx.x * BM;
    const int kbase = blockIdx.y * BN;
    const uint32_t sb = smem_u32(dyn_smem);
    float* s_cbn = (float*)(dyn_smem + SMEM_CBN);

    if (tid < BN) s_cbn[tid] = g_cbnorm[kbase + tid];

    copy_chunk(sb, 0, row0, kbase, tid);
    CP_COMMIT();

    float c[2][8][4];
#pragma unroll
    for (int i = 0; i < 2; i++)
#pragma unroll
        for (int j = 0; j < 8; j++)
#pragma unroll
            for (int q = 0; q < 4; q++) c[i][j][q] = 0.f;

    for (int ch = 0; ch < NCHUNK; ch++) {
        if (ch + 1 < NCHUNK) {
            copy_chunk(sb + ((ch + 1) & 1) * STAGE_BYTES, ch + 1, row0, kbase, tid);
            CP_COMMIT();
            CP_WAIT(1);
        } else {
            CP_WAIT(0);
        }
        __syncthreads();

        const uint32_t st = sb + (ch & 1) * STAGE_BYTES;
#pragma unroll
        for (int ks = 0; ks < KC / 16; ks++) {
            uint32_t a[2][4];
#pragma unroll
            for (int i = 0; i < 2; i++) {
                uint32_t addr = st + A_OFF +
                    SWZ((uint32_t)((wm * 32 + i * 16 + (lane & 15)) * 128 +
                                   ks * 32 + (lane >> 4) * 16));
                LDSM4(a[i][0], a[i][1], a[i][2], a[i][3], addr);
            }
#pragma unroll
            for (int j = 0; j < 4; j++) {
                uint32_t b0, b1, b2, b3;
                uint32_t addr = st + B_OFF +
                    SWZ((uint32_t)((wn * 64 + j * 16 + (lane & 15)) * 128 +
                                   ks * 32 + (lane >> 4) * 16));
                LDSM4(b0, b1, b2, b3, addr);
#pragma unroll
                for (int i = 0; i < 2; i++) {
                    MMA_BF16(c[i][2 * j + 0], a[i], b0, b2);
                    MMA_BF16(c[i][2 * j + 1], a[i], b1, b3);
                }
            }
        }
        __syncthreads();
    }

    // ---- Epilogue: score = cbnorm - 2*dot; per-row top-3 ----
    float tv[4][3];
    int   ti[4][3];
#pragma unroll
    for (int r = 0; r < 4; r++)
#pragma unroll
        for (int k = 0; k < 3; k++) { tv[r][k] = 3.4e38f; ti[r][k] = 0; }

#pragma unroll
    for (int i = 0; i < 2; i++)
#pragma unroll
        for (int jj = 0; jj < 8; jj++)
#pragma unroll
            for (int q = 0; q < 4; q++) {
                int col = wn * 64 + jj * 8 + (lane & 3) * 2 + (q & 1);
                float s = fmaf(-2.f, c[i][jj][q], s_cbn[col]);
                int ri = i * 2 + (q >> 1);
                ins3(tv[ri], ti[ri], s, kbase + col);
            }

    // merge across the 4 lanes sharing each row (lanes differ in lane&3)
#pragma unroll
    for (int off = 1; off <= 2; off <<= 1) {
#pragma unroll
        for (int r = 0; r < 4; r++) {
            float pv[3]; int pi[3];
#pragma unroll
            for (int k = 0; k < 3; k++) {
                pv[k] = __shfl_xor_sync(0xffffffffu, tv[r][k], off);
                pi[k] = __shfl_xor_sync(0xffffffffu, ti[r][k], off);
            }
#pragma unroll
            for (int k = 0; k < 3; k++) ins3(tv[r], ti[r], pv[k], pi[k]);
        }
    }

    // stage per-(row, wn) lists into smem (reuse stage region)
    float* smv = (float*)dyn_smem;               // [64][4][3]
    int*   smi = (int*)(dyn_smem + 64 * 4 * 3 * 4);
    if ((lane & 3) == 0) {
        int g = lane >> 2;
#pragma unroll
        for (int i = 0; i < 2; i++)
#pragma unroll
            for (int sub = 0; sub < 2; sub++) {
                int ri = i * 2 + sub;
                int r = wm * 32 + i * 16 + g + sub * 8;
#pragma unroll
                for (int k = 0; k < 3; k++) {
                    smv[(r * 4 + wn) * 3 + k] = tv[ri][k];
                    smi[(r * 4 + wn) * 3 + k] = ti[ri][k];
                }
            }
    }
    __syncthreads();

    if (tid < BM) {
        float fv[3] = {3.4e38f, 3.4e38f, 3.4e38f};
        int   fi[3] = {0, 0, 0};
#pragma unroll
        for (int w = 0; w < 4; w++)
#pragma unroll
            for (int k = 0; k < 3; k++)
                ins3(fv, fi, smv[(tid * 4 + w) * 3 + k], smi[(tid * 4 + w) * 3 + k]);
        size_t base = ((size_t)blockIdx.y * NROWS + row0 + tid) * 3;
#pragma unroll
        for (int k = 0; k < 3; k++) {
            g_tval[base + k] = fv[k];
            g_tidx[base + k] = fi[k];
        }
    }
}

// ---------------------------------------------------------------------------
// Refine: exact fp32 re-scoring; gather zq, indices, loss, counts; the last
// block to finish also computes the scalar outputs (fence+ticket pattern).
// Warp per row, 8 rows per block.
// ---------------------------------------------------------------------------
__global__ void refine_kernel(const float* __restrict__ ze,
                              const float* __restrict__ cb,
                              float* __restrict__ out) {
    const int warp = threadIdx.x >> 5, lane = threadIdx.x & 31;
    const int row = blockIdx.x * 8 + warp;

    // global min of approximate candidate scores
    float vmin = 3.4e38f;
#pragma unroll 4
    for (int s = 0; s < KSPLIT; s++) {
        size_t base = ((size_t)s * NROWS + row) * 3;
#pragma unroll
        for (int k = 0; k < 3; k++) vmin = fminf(vmin, g_tval[base + k]);
    }

    const float4* zef = (const float4*)ze;
    const float4* cbf = (const float4*)cb;
    float bestv = 3.4e38f;
    int   besti = 0x7fffffff;

    for (int s = 0; s < KSPLIT; s++) {
        size_t base = ((size_t)s * NROWS + row) * 3;
#pragma unroll
        for (int k = 0; k < 3; k++) {
            float av = g_tval[base + k];
            if (av <= vmin + MARGIN) {
                int idx = g_tidx[base + k];
                float dot = 0.f;
#pragma unroll
                for (int u = 0; u < 2; u++) {
                    float4 z = zef[(size_t)row * 64 + lane * 2 + u];
                    float4 e = cbf[(size_t)idx * 64 + lane * 2 + u];
                    dot = fmaf(z.x, e.x, dot);
                    dot = fmaf(z.y, e.y, dot);
                    dot = fmaf(z.z, e.z, dot);
                    dot = fmaf(z.w, e.w, dot);
                }
#pragma unroll
                for (int o = 16; o; o >>= 1)
                    dot += __shfl_xor_sync(0xffffffffu, dot, o);
                float sc = fmaf(-2.f, dot, g_cbnorm[idx]);
                if (sc < bestv || (sc == bestv && idx < besti)) {
                    bestv = sc; besti = idx;
                }
            }
        }
    }

    if (lane == 0) {
        out[row] = (float)besti;
        atomicAdd(&g_counts[besti], 1);
    }

    const float* zr = ze + (size_t)row * D;
    const float* cr = cb + (size_t)besti * D;
    float* qr = out + NROWS + (size_t)row * D;
    float sl = 0.f;
#pragma unroll
    for (int i = 0; i < D / 32; i++) {
        float cv = cr[lane + i * 32];
        float zv = zr[lane + i * 32];
        qr[lane + i * 32] = cv;
        float dd = cv - zv;
        sl = fmaf(dd, dd, sl);
    }
#pragma unroll
    for (int o = 16; o; o >>= 1) sl += __shfl_xor_sync(0xffffffffu, sl, o);
    if (lane == 0) atomicAdd(&g_loss, sl);

    // ---- last-block finalize ----
    __threadfence();
    __syncthreads();
    __shared__ unsigned int s_ticket;
    if (threadIdx.x == 0) s_ticket = atomicAdd(&g_done, 1u);
    __syncthreads();
    if (s_ticket == gridDim.x - 1) {
        __shared__ float red[256];
        float h = 0.f;
        for (int k = threadIdx.x; k < KCODES; k += 256) {
            float p = (float)g_counts[k] / 10.0f;
            h += p * logf(p + 1e-10f);
        }
        red[threadIdx.x] = h;
        __syncthreads();
        for (int o = 128; o; o >>= 1) {
            if (threadIdx.x < o) red[threadIdx.x] += red[threadIdx.x + o];
            __syncthreads();
        }
        if (threadIdx.x == 0) {
            float loss = g_loss / (float)((size_t)NROWS * D);
            const size_t base = (size_t)NROWS + (size_t)NROWS * D;
            out[base + 0] = loss;
            out[base + 1] = loss;
            out[base + 2] = expf(-red[0]);
        }
    }
}

// ---------------------------------------------------------------------------
extern "C" void kernel_launch(void* const* d_in, const int* in_sizes, int n_in,
                              void* d_out, int out_size) {
    const float* ze = (const float*)d_in[0];
    const float* cb = (const float*)d_in[1];
    float* out = (float*)d_out;

    cudaFuncSetAttribute(pass1_kernel,
                         cudaFuncAttributeMaxDynamicSharedMemorySize, SMEM_TOTAL);

    conv_ze_kernel<<<(NROWS * D / 4) / 256, 256>>>(ze);
    prep_cb_kernel<<<KCODES / 8, 256>>>(cb);

    dim3 grid(NROWS / BM, KSPLIT);
    pass1_kernel<<<grid, 256, SMEM_TOTAL>>>();

    refine_kernel<<<NROWS / 8, 256>>>(ze, cb, out);
}